// round 1
// baseline (speedup 1.0000x reference)
#include <cuda_runtime.h>
#include <math.h>

#define BB 8
#define SS 2048
#define DD 256
#define HH 4
#define DHH 64
#define BSR (BB*SS)   // 16384 rows

// ---------------- scratch (no allocations allowed) ----------------
__device__ float g_q[BB*HH*SS*DHH];
__device__ float g_k[BB*HH*SS*DHH];
__device__ float g_v[BB*HH*SS*DHH];
__device__ float g_ctx[BSR*DD];

// =====================================================================
// QKV projection: out_z[b,h,s,dh] = sum_k x[bs,k] * w_z[k, h*64+dh]
// grid: (DD/64, BSR/128, 3), 256 threads. Tile 128x64, BK=16, thread 8x4.
// =====================================================================
__global__ __launch_bounds__(256) void qkv_kernel(
    const float* __restrict__ x,
    const float* __restrict__ wq,
    const float* __restrict__ wk,
    const float* __restrict__ wv)
{
    __shared__ float Xt[16][129];   // transposed x tile [k][row], padded
    __shared__ float Ws[16][64];    // w tile [k][n]

    const int tid = threadIdx.x;
    const int ty = tid >> 4;        // 0..15
    const int tx = tid & 15;        // 0..15
    const int n0 = blockIdx.x * 64;
    const int row0 = blockIdx.y * 128;
    const int z = blockIdx.z;

    const float* w = (z == 0) ? wq : (z == 1) ? wk : wv;
    float* outp = (z == 0) ? g_q : (z == 1) ? g_k : g_v;

    float acc[8][4];
#pragma unroll
    for (int i = 0; i < 8; i++)
#pragma unroll
        for (int j = 0; j < 4; j++) acc[i][j] = 0.f;

    for (int k0 = 0; k0 < DD; k0 += 16) {
        // X tile: 128 rows x 16 k = 512 float4, 2 per thread (stored transposed)
#pragma unroll
        for (int r = 0; r < 2; r++) {
            int f = tid + 256 * r;
            int row = f >> 2;          // 0..127
            int kg = f & 3;            // 0..3
            float4 v4 = *reinterpret_cast<const float4*>(&x[(row0 + row) * DD + k0 + kg * 4]);
            Xt[kg * 4 + 0][row] = v4.x;
            Xt[kg * 4 + 1][row] = v4.y;
            Xt[kg * 4 + 2][row] = v4.z;
            Xt[kg * 4 + 3][row] = v4.w;
        }
        // W tile: 16 rows x 64 n = 256 float4, 1 per thread
        {
            int rowk = tid >> 4;
            int c4 = tid & 15;
            *reinterpret_cast<float4*>(&Ws[rowk][c4 * 4]) =
                *reinterpret_cast<const float4*>(&w[(k0 + rowk) * DD + n0 + c4 * 4]);
        }
        __syncthreads();
#pragma unroll
        for (int kk = 0; kk < 16; kk++) {
            float a[8];
#pragma unroll
            for (int i = 0; i < 8; i++) a[i] = Xt[kk][ty * 8 + i];
            float4 b4 = *reinterpret_cast<const float4*>(&Ws[kk][tx * 4]);
            float bb[4] = {b4.x, b4.y, b4.z, b4.w};
#pragma unroll
            for (int i = 0; i < 8; i++)
#pragma unroll
                for (int j = 0; j < 4; j++) acc[i][j] += a[i] * bb[j];
        }
        __syncthreads();
    }

    // write into [b, h, s, dh] (n-tile of 64 == one head)
    const int h = n0 / DHH;
#pragma unroll
    for (int i = 0; i < 8; i++) {
        int bsrow = row0 + ty * 8 + i;
        int b_ = bsrow >> 11;          // / 2048
        int s_ = bsrow & (SS - 1);
        float4 v4 = make_float4(acc[i][0], acc[i][1], acc[i][2], acc[i][3]);
        *reinterpret_cast<float4*>(&outp[(((b_ * HH + h) * SS) + s_) * DHH + tx * 4]) = v4;
    }
}

// =====================================================================
// Flash attention, fp32. grid: (S/64, B*H), 256 threads.
// Q tile 64 rows, K/V tiles 32 rows, online softmax.
// =====================================================================
__global__ __launch_bounds__(256) void attn_kernel()
{
    __shared__ float Qt[DHH][65];   // Qt[d][q]
    __shared__ float Kt[DHH][33];   // Kt[d][k]
    __shared__ float Vs[32][DHH];   // Vs[k][d]
    __shared__ float Ps[64][33];    // P[q][k]

    const int tid = threadIdx.x;
    const int ty = tid >> 4;        // 0..15 -> 4 q rows
    const int tx = tid & 15;        // 0..15 -> 2 k cols / 4 dh cols
    const int q0 = blockIdx.x * 64;
    const int bh = blockIdx.y;

    const float* qptr = g_q + (size_t)bh * SS * DHH;
    const float* kptr = g_k + (size_t)bh * SS * DHH;
    const float* vptr = g_v + (size_t)bh * SS * DHH;

    // load Q tile transposed: 64x64 = 1024 float4, 4 per thread
#pragma unroll
    for (int r = 0; r < 4; r++) {
        int f = tid + 256 * r;
        int row = f >> 4;           // 0..63
        int c4 = f & 15;            // 0..15
        float4 v4 = *reinterpret_cast<const float4*>(&qptr[(q0 + row) * DHH + c4 * 4]);
        Qt[c4 * 4 + 0][row] = v4.x;
        Qt[c4 * 4 + 1][row] = v4.y;
        Qt[c4 * 4 + 2][row] = v4.z;
        Qt[c4 * 4 + 3][row] = v4.w;
    }

    float O[4][4];
    float m[4], l[4];
#pragma unroll
    for (int i = 0; i < 4; i++) {
        m[i] = -INFINITY;
        l[i] = 0.f;
#pragma unroll
        for (int j = 0; j < 4; j++) O[i][j] = 0.f;
    }

    const float scale = 0.125f;     // 1/sqrt(64)

    for (int kt = 0; kt < SS / 32; kt++) {
        const int k0 = kt * 32;
        __syncthreads();            // prior reads of Kt/Vs/Ps done
        // load K (transposed) and V tiles: each 32x64 = 512 float4, 2 per thread
#pragma unroll
        for (int r = 0; r < 2; r++) {
            int f = tid + 256 * r;
            int row = f >> 4;       // 0..31
            int c4 = f & 15;
            float4 kv = *reinterpret_cast<const float4*>(&kptr[(k0 + row) * DHH + c4 * 4]);
            Kt[c4 * 4 + 0][row] = kv.x;
            Kt[c4 * 4 + 1][row] = kv.y;
            Kt[c4 * 4 + 2][row] = kv.z;
            Kt[c4 * 4 + 3][row] = kv.w;
            float4 vv = *reinterpret_cast<const float4*>(&vptr[(k0 + row) * DHH + c4 * 4]);
            *reinterpret_cast<float4*>(&Vs[row][c4 * 4]) = vv;
        }
        __syncthreads();

        // scores: [64 q x 32 k], thread computes 4x2
        float sa[4][2];
#pragma unroll
        for (int i = 0; i < 4; i++) { sa[i][0] = 0.f; sa[i][1] = 0.f; }
#pragma unroll 4
        for (int d = 0; d < DHH; d++) {
            float a0 = Qt[d][ty * 4 + 0];
            float a1 = Qt[d][ty * 4 + 1];
            float a2 = Qt[d][ty * 4 + 2];
            float a3 = Qt[d][ty * 4 + 3];
            float b0 = Kt[d][tx * 2 + 0];
            float b1 = Kt[d][tx * 2 + 1];
            sa[0][0] += a0 * b0; sa[0][1] += a0 * b1;
            sa[1][0] += a1 * b0; sa[1][1] += a1 * b1;
            sa[2][0] += a2 * b0; sa[2][1] += a2 * b1;
            sa[3][0] += a3 * b0; sa[3][1] += a3 * b1;
        }

        // online softmax per row (reduce across the 16 tx lanes, width-16 shuffles)
#pragma unroll
        for (int i = 0; i < 4; i++) {
            float s0 = sa[i][0] * scale;
            float s1 = sa[i][1] * scale;
            float mx = fmaxf(s0, s1);
#pragma unroll
            for (int off = 1; off < 16; off <<= 1)
                mx = fmaxf(mx, __shfl_xor_sync(0xffffffffu, mx, off, 16));
            float m_new = fmaxf(m[i], mx);
            float alpha = __expf(m[i] - m_new);
            float p0 = __expf(s0 - m_new);
            float p1 = __expf(s1 - m_new);
            float rs = p0 + p1;
#pragma unroll
            for (int off = 1; off < 16; off <<= 1)
                rs += __shfl_xor_sync(0xffffffffu, rs, off, 16);
            l[i] = l[i] * alpha + rs;
            m[i] = m_new;
#pragma unroll
            for (int j = 0; j < 4; j++) O[i][j] *= alpha;
            Ps[ty * 4 + i][tx * 2 + 0] = p0;
            Ps[ty * 4 + i][tx * 2 + 1] = p1;
        }
        __syncthreads();

        // O += P @ V : [64 q x 64 dh], k-depth 32, thread 4x4
#pragma unroll 4
        for (int kk = 0; kk < 32; kk++) {
            float a0 = Ps[ty * 4 + 0][kk];
            float a1 = Ps[ty * 4 + 1][kk];
            float a2 = Ps[ty * 4 + 2][kk];
            float a3 = Ps[ty * 4 + 3][kk];
            float4 b4 = *reinterpret_cast<const float4*>(&Vs[kk][tx * 4]);
            O[0][0] += a0 * b4.x; O[0][1] += a0 * b4.y; O[0][2] += a0 * b4.z; O[0][3] += a0 * b4.w;
            O[1][0] += a1 * b4.x; O[1][1] += a1 * b4.y; O[1][2] += a1 * b4.z; O[1][3] += a1 * b4.w;
            O[2][0] += a2 * b4.x; O[2][1] += a2 * b4.y; O[2][2] += a2 * b4.z; O[2][3] += a2 * b4.w;
            O[3][0] += a3 * b4.x; O[3][1] += a3 * b4.y; O[3][2] += a3 * b4.z; O[3][3] += a3 * b4.w;
        }
    }

    // normalize and write ctx[bs, h*64 + dh]
    const int b_ = bh >> 2;     // / H
    const int h_ = bh & 3;      // % H
#pragma unroll
    for (int i = 0; i < 4; i++) {
        float inv = 1.0f / l[i];
        int srow = q0 + ty * 4 + i;
        float4 v4 = make_float4(O[i][0] * inv, O[i][1] * inv, O[i][2] * inv, O[i][3] * inv);
        *reinterpret_cast<float4*>(&g_ctx[((size_t)(b_ * SS + srow)) * DD + h_ * DHH + tx * 4]) = v4;
    }
}

// =====================================================================
// Output projection: out = ctx @ w_o + b_o
// grid: (DD/64, BSR/128), 256 threads. Same tiling as qkv_kernel.
// =====================================================================
__global__ __launch_bounds__(256) void out_proj_kernel(
    const float* __restrict__ wo,
    const float* __restrict__ bo,
    float* __restrict__ out)
{
    __shared__ float Xt[16][129];
    __shared__ float Ws[16][64];

    const int tid = threadIdx.x;
    const int ty = tid >> 4;
    const int tx = tid & 15;
    const int n0 = blockIdx.x * 64;
    const int row0 = blockIdx.y * 128;

    float acc[8][4];
#pragma unroll
    for (int i = 0; i < 8; i++)
#pragma unroll
        for (int j = 0; j < 4; j++) acc[i][j] = 0.f;

    for (int k0 = 0; k0 < DD; k0 += 16) {
#pragma unroll
        for (int r = 0; r < 2; r++) {
            int f = tid + 256 * r;
            int row = f >> 2;
            int kg = f & 3;
            float4 v4 = *reinterpret_cast<const float4*>(&g_ctx[(size_t)(row0 + row) * DD + k0 + kg * 4]);
            Xt[kg * 4 + 0][row] = v4.x;
            Xt[kg * 4 + 1][row] = v4.y;
            Xt[kg * 4 + 2][row] = v4.z;
            Xt[kg * 4 + 3][row] = v4.w;
        }
        {
            int rowk = tid >> 4;
            int c4 = tid & 15;
            *reinterpret_cast<float4*>(&Ws[rowk][c4 * 4]) =
                *reinterpret_cast<const float4*>(&wo[(k0 + rowk) * DD + n0 + c4 * 4]);
        }
        __syncthreads();
#pragma unroll
        for (int kk = 0; kk < 16; kk++) {
            float a[8];
#pragma unroll
            for (int i = 0; i < 8; i++) a[i] = Xt[kk][ty * 8 + i];
            float4 b4 = *reinterpret_cast<const float4*>(&Ws[kk][tx * 4]);
            float bb[4] = {b4.x, b4.y, b4.z, b4.w};
#pragma unroll
            for (int i = 0; i < 8; i++)
#pragma unroll
                for (int j = 0; j < 4; j++) acc[i][j] += a[i] * bb[j];
        }
        __syncthreads();
    }

    float4 bias = *reinterpret_cast<const float4*>(&bo[n0 + tx * 4]);
#pragma unroll
    for (int i = 0; i < 8; i++) {
        int bsrow = row0 + ty * 8 + i;
        float4 v4 = make_float4(acc[i][0] + bias.x, acc[i][1] + bias.y,
                                acc[i][2] + bias.z, acc[i][3] + bias.w);
        *reinterpret_cast<float4*>(&out[(size_t)bsrow * DD + n0 + tx * 4]) = v4;
    }
}

// =====================================================================
extern "C" void kernel_launch(void* const* d_in, const int* in_sizes, int n_in,
                              void* d_out, int out_size)
{
    const float* x  = (const float*)d_in[0];
    const float* wq = (const float*)d_in[1];
    const float* wk = (const float*)d_in[2];
    const float* wv = (const float*)d_in[3];
    const float* wo = (const float*)d_in[4];
    const float* bo = (const float*)d_in[5];
    float* out = (float*)d_out;

    qkv_kernel<<<dim3(DD / 64, BSR / 128, 3), 256>>>(x, wq, wk, wv);
    attn_kernel<<<dim3(SS / 64, BB * HH), 256>>>();
    out_proj_kernel<<<dim3(DD / 64, BSR / 128), 256>>>(wo, bo, out);
}

// round 2
// speedup vs baseline: 2.4841x; 2.4841x over previous
#include <cuda_runtime.h>
#include <math.h>

#define BB 8
#define SS 2048
#define DD 256
#define HH 4
#define DHH 64
#define BSR (BB*SS)   // 16384 rows

// ---------------- scratch (no allocations allowed) ----------------
__device__ float g_q[BB*HH*SS*DHH];
__device__ float g_k[BB*HH*SS*DHH];
__device__ float g_v[BB*HH*SS*DHH];
__device__ float g_ctx[BSR*DD];

// round-to-nearest tf32 (keeps bits in a float register)
__device__ __forceinline__ float t32(float x) {
    unsigned u;
    asm("cvt.rna.tf32.f32 %0, %1;" : "=r"(u) : "f"(x));
    return __uint_as_float(u);
}

__device__ __forceinline__ void mma_tf32(float* c, const unsigned* a, const unsigned* b) {
    asm volatile(
        "mma.sync.aligned.m16n8k8.row.col.f32.tf32.tf32.f32 "
        "{%0,%1,%2,%3}, {%4,%5,%6,%7}, {%8,%9}, {%0,%1,%2,%3};"
        : "+f"(c[0]), "+f"(c[1]), "+f"(c[2]), "+f"(c[3])
        : "r"(a[0]), "r"(a[1]), "r"(a[2]), "r"(a[3]), "r"(b[0]), "r"(b[1]));
}

// =====================================================================
// QKV projection (fp32 SIMT): out_z[b,h,s,dh] = sum_k x[bs,k] * w_z[k, h*64+dh]
// grid: (DD/64, BSR/128, 3), 256 threads.
// =====================================================================
__global__ __launch_bounds__(256) void qkv_kernel(
    const float* __restrict__ x,
    const float* __restrict__ wq,
    const float* __restrict__ wk,
    const float* __restrict__ wv)
{
    __shared__ float Xt[16][129];
    __shared__ float Ws[16][64];

    const int tid = threadIdx.x;
    const int ty = tid >> 4;
    const int tx = tid & 15;
    const int n0 = blockIdx.x * 64;
    const int row0 = blockIdx.y * 128;
    const int z = blockIdx.z;

    const float* w = (z == 0) ? wq : (z == 1) ? wk : wv;
    float* outp = (z == 0) ? g_q : (z == 1) ? g_k : g_v;

    float acc[8][4];
#pragma unroll
    for (int i = 0; i < 8; i++)
#pragma unroll
        for (int j = 0; j < 4; j++) acc[i][j] = 0.f;

    for (int k0 = 0; k0 < DD; k0 += 16) {
#pragma unroll
        for (int r = 0; r < 2; r++) {
            int f = tid + 256 * r;
            int row = f >> 2;
            int kg = f & 3;
            float4 v4 = *reinterpret_cast<const float4*>(&x[(row0 + row) * DD + k0 + kg * 4]);
            Xt[kg * 4 + 0][row] = v4.x;
            Xt[kg * 4 + 1][row] = v4.y;
            Xt[kg * 4 + 2][row] = v4.z;
            Xt[kg * 4 + 3][row] = v4.w;
        }
        {
            int rowk = tid >> 4;
            int c4 = tid & 15;
            *reinterpret_cast<float4*>(&Ws[rowk][c4 * 4]) =
                *reinterpret_cast<const float4*>(&w[(k0 + rowk) * DD + n0 + c4 * 4]);
        }
        __syncthreads();
#pragma unroll
        for (int kk = 0; kk < 16; kk++) {
            float a[8];
#pragma unroll
            for (int i = 0; i < 8; i++) a[i] = Xt[kk][ty * 8 + i];
            float4 b4 = *reinterpret_cast<const float4*>(&Ws[kk][tx * 4]);
            float bb[4] = {b4.x, b4.y, b4.z, b4.w};
#pragma unroll
            for (int i = 0; i < 8; i++)
#pragma unroll
                for (int j = 0; j < 4; j++) acc[i][j] += a[i] * bb[j];
        }
        __syncthreads();
    }

    const int h = n0 / DHH;
#pragma unroll
    for (int i = 0; i < 8; i++) {
        int bsrow = row0 + ty * 8 + i;
        int b_ = bsrow >> 11;
        int s_ = bsrow & (SS - 1);
        float4 v4 = make_float4(acc[i][0], acc[i][1], acc[i][2], acc[i][3]);
        *reinterpret_cast<float4*>(&outp[(((b_ * HH + h) * SS) + s_) * DHH + tx * 4]) = v4;
    }
}

// =====================================================================
// Flash attention with tf32 tensor-core MMA.
// grid: (S/128, B*H), 256 threads (8 warps, each owns 16 q-rows).
// Q-tile 128, K-tile 64. Dynamic smem:
//   QP (Q then P) : 128 x stride68  = 8704 floats
//   Ks            :  64 x stride68  = 4352 floats
//   Vs            :  64 x stride72  = 4608 floats
// total 17664 floats = 70656 B
// =====================================================================
#define ATTN_SMEM_BYTES 70656

__global__ __launch_bounds__(256) void attn_tf32_kernel()
{
    extern __shared__ float sm[];
    float* QP = sm;                 // stride 68
    float* Ks = sm + 8704;          // stride 68
    float* Vs = sm + 13056;         // stride 72

    const int tid = threadIdx.x;
    const int lane = tid & 31;
    const int warp = tid >> 5;
    const int gr = lane >> 2;       // 0..7
    const int gc = lane & 3;        // 0..3
    const int wq = warp * 16;

    const int q0 = blockIdx.x * 128;
    const int bh = blockIdx.y;

    const float* qptr = g_q + (size_t)bh * SS * DHH;
    const float* kptr = g_k + (size_t)bh * SS * DHH;
    const float* vptr = g_v + (size_t)bh * SS * DHH;

    // ---- load Q tile (scaled by 1/sqrt(dh), tf32-rounded) ----
#pragma unroll
    for (int r = 0; r < 8; r++) {
        int f = tid + 256 * r;
        int row = f >> 4;
        int c4 = f & 15;
        float4 v4 = *reinterpret_cast<const float4*>(&qptr[(q0 + row) * DHH + c4 * 4]);
        float4 w4 = make_float4(t32(v4.x * 0.125f), t32(v4.y * 0.125f),
                                t32(v4.z * 0.125f), t32(v4.w * 0.125f));
        *reinterpret_cast<float4*>(&QP[row * 68 + c4 * 4]) = w4;
    }
    __syncthreads();

    // ---- extract Q fragments (register-resident for whole K loop) ----
    unsigned qa[8][4];
#pragma unroll
    for (int ks = 0; ks < 8; ks++) {
        int col = ks * 8 + gc;
        qa[ks][0] = __float_as_uint(QP[(wq + gr) * 68 + col]);
        qa[ks][1] = __float_as_uint(QP[(wq + 8 + gr) * 68 + col]);
        qa[ks][2] = __float_as_uint(QP[(wq + gr) * 68 + col + 4]);
        qa[ks][3] = __float_as_uint(QP[(wq + 8 + gr) * 68 + col + 4]);
    }

    float o[8][4];
#pragma unroll
    for (int nt = 0; nt < 8; nt++)
#pragma unroll
        for (int j = 0; j < 4; j++) o[nt][j] = 0.f;
    float m0 = -INFINITY, m1 = -INFINITY, l0 = 0.f, l1 = 0.f;

    for (int kt = 0; kt < SS / 64; kt++) {
        const int k0 = kt * 64;
        __syncthreads();   // Q-frag extraction (iter 0) / prior-iter Ks,Vs reads done

        // ---- load K, V tiles (tf32-rounded) ----
#pragma unroll
        for (int r = 0; r < 4; r++) {
            int f = tid + 256 * r;
            int row = f >> 4;
            int c4 = f & 15;
            float4 kv = *reinterpret_cast<const float4*>(&kptr[(k0 + row) * DHH + c4 * 4]);
            float4 kw = make_float4(t32(kv.x), t32(kv.y), t32(kv.z), t32(kv.w));
            *reinterpret_cast<float4*>(&Ks[row * 68 + c4 * 4]) = kw;
            float4 vv = *reinterpret_cast<const float4*>(&vptr[(k0 + row) * DHH + c4 * 4]);
            float4 vw = make_float4(t32(vv.x), t32(vv.y), t32(vv.z), t32(vv.w));
            *reinterpret_cast<float4*>(&Vs[row * 72 + c4 * 4]) = vw;
        }
        __syncthreads();

        // ---- S = Q @ K^T  (m16 x n64 x k64 per warp) ----
        float s[8][4];
#pragma unroll
        for (int nt = 0; nt < 8; nt++) {
            s[nt][0] = 0.f; s[nt][1] = 0.f; s[nt][2] = 0.f; s[nt][3] = 0.f;
#pragma unroll
            for (int ks = 0; ks < 8; ks++) {
                unsigned b[2];
                b[0] = __float_as_uint(Ks[(nt * 8 + gr) * 68 + ks * 8 + gc]);
                b[1] = __float_as_uint(Ks[(nt * 8 + gr) * 68 + ks * 8 + gc + 4]);
                mma_tf32(s[nt], qa[ks], b);
            }
        }

        // ---- online softmax (rows r0 = wq+gr, r1 = wq+8+gr) ----
        float mx0 = -INFINITY, mx1 = -INFINITY;
#pragma unroll
        for (int nt = 0; nt < 8; nt++) {
            mx0 = fmaxf(mx0, fmaxf(s[nt][0], s[nt][1]));
            mx1 = fmaxf(mx1, fmaxf(s[nt][2], s[nt][3]));
        }
        mx0 = fmaxf(mx0, __shfl_xor_sync(0xffffffffu, mx0, 1));
        mx0 = fmaxf(mx0, __shfl_xor_sync(0xffffffffu, mx0, 2));
        mx1 = fmaxf(mx1, __shfl_xor_sync(0xffffffffu, mx1, 1));
        mx1 = fmaxf(mx1, __shfl_xor_sync(0xffffffffu, mx1, 2));

        float m0n = fmaxf(m0, mx0);
        float m1n = fmaxf(m1, mx1);
        float a0 = __expf(m0 - m0n);
        float a1 = __expf(m1 - m1n);

        float rs0 = 0.f, rs1 = 0.f;
#pragma unroll
        for (int nt = 0; nt < 8; nt++) {
            float p0 = __expf(s[nt][0] - m0n);
            float p1 = __expf(s[nt][1] - m0n);
            float p2 = __expf(s[nt][2] - m1n);
            float p3 = __expf(s[nt][3] - m1n);
            rs0 += p0 + p1;
            rs1 += p2 + p3;
            float2 lo = make_float2(t32(p0), t32(p1));
            float2 hi = make_float2(t32(p2), t32(p3));
            *reinterpret_cast<float2*>(&QP[(wq + gr) * 68 + nt * 8 + gc * 2]) = lo;
            *reinterpret_cast<float2*>(&QP[(wq + 8 + gr) * 68 + nt * 8 + gc * 2]) = hi;
        }
        rs0 += __shfl_xor_sync(0xffffffffu, rs0, 1);
        rs0 += __shfl_xor_sync(0xffffffffu, rs0, 2);
        rs1 += __shfl_xor_sync(0xffffffffu, rs1, 1);
        rs1 += __shfl_xor_sync(0xffffffffu, rs1, 2);

        m0 = m0n; m1 = m1n;
        l0 = l0 * a0 + rs0;
        l1 = l1 * a1 + rs1;
#pragma unroll
        for (int nt = 0; nt < 8; nt++) {
            o[nt][0] *= a0; o[nt][1] *= a0;
            o[nt][2] *= a1; o[nt][3] *= a1;
        }
        __syncwarp();   // P rows of this warp written by this warp only

        // ---- O += P @ V  (m16 x n64 x k64 per warp) ----
#pragma unroll
        for (int ks = 0; ks < 8; ks++) {
            unsigned pa[4];
            int col = ks * 8 + gc;
            pa[0] = __float_as_uint(QP[(wq + gr) * 68 + col]);
            pa[1] = __float_as_uint(QP[(wq + 8 + gr) * 68 + col]);
            pa[2] = __float_as_uint(QP[(wq + gr) * 68 + col + 4]);
            pa[3] = __float_as_uint(QP[(wq + 8 + gr) * 68 + col + 4]);
#pragma unroll
            for (int nt = 0; nt < 8; nt++) {
                unsigned b[2];
                b[0] = __float_as_uint(Vs[(ks * 8 + gc) * 72 + nt * 8 + gr]);
                b[1] = __float_as_uint(Vs[(ks * 8 + gc + 4) * 72 + nt * 8 + gr]);
                mma_tf32(o[nt], pa, b);
            }
        }
    }

    // ---- epilogue: normalize, write ctx[bs, h*64 + dh] ----
    const float inv0 = 1.0f / l0;
    const float inv1 = 1.0f / l1;
    const int b_ = bh >> 2;
    const int h_ = bh & 3;
    const int row0 = q0 + wq + gr;
    const int row1 = row0 + 8;
#pragma unroll
    for (int nt = 0; nt < 8; nt++) {
        int col = h_ * DHH + nt * 8 + gc * 2;
        float2 lo = make_float2(o[nt][0] * inv0, o[nt][1] * inv0);
        float2 hi = make_float2(o[nt][2] * inv1, o[nt][3] * inv1);
        *reinterpret_cast<float2*>(&g_ctx[(size_t)(b_ * SS + row0) * DD + col]) = lo;
        *reinterpret_cast<float2*>(&g_ctx[(size_t)(b_ * SS + row1) * DD + col]) = hi;
    }
}

// =====================================================================
// Output projection: out = ctx @ w_o + b_o (fp32 SIMT)
// =====================================================================
__global__ __launch_bounds__(256) void out_proj_kernel(
    const float* __restrict__ wo,
    const float* __restrict__ bo,
    float* __restrict__ out)
{
    __shared__ float Xt[16][129];
    __shared__ float Ws[16][64];

    const int tid = threadIdx.x;
    const int ty = tid >> 4;
    const int tx = tid & 15;
    const int n0 = blockIdx.x * 64;
    const int row0 = blockIdx.y * 128;

    float acc[8][4];
#pragma unroll
    for (int i = 0; i < 8; i++)
#pragma unroll
        for (int j = 0; j < 4; j++) acc[i][j] = 0.f;

    for (int k0 = 0; k0 < DD; k0 += 16) {
#pragma unroll
        for (int r = 0; r < 2; r++) {
            int f = tid + 256 * r;
            int row = f >> 2;
            int kg = f & 3;
            float4 v4 = *reinterpret_cast<const float4*>(&g_ctx[(size_t)(row0 + row) * DD + k0 + kg * 4]);
            Xt[kg * 4 + 0][row] = v4.x;
            Xt[kg * 4 + 1][row] = v4.y;
            Xt[kg * 4 + 2][row] = v4.z;
            Xt[kg * 4 + 3][row] = v4.w;
        }
        {
            int rowk = tid >> 4;
            int c4 = tid & 15;
            *reinterpret_cast<float4*>(&Ws[rowk][c4 * 4]) =
                *reinterpret_cast<const float4*>(&wo[(k0 + rowk) * DD + n0 + c4 * 4]);
        }
        __syncthreads();
#pragma unroll
        for (int kk = 0; kk < 16; kk++) {
            float a[8];
#pragma unroll
            for (int i = 0; i < 8; i++) a[i] = Xt[kk][ty * 8 + i];
            float4 b4 = *reinterpret_cast<const float4*>(&Ws[kk][tx * 4]);
            float bb[4] = {b4.x, b4.y, b4.z, b4.w};
#pragma unroll
            for (int i = 0; i < 8; i++)
#pragma unroll
                for (int j = 0; j < 4; j++) acc[i][j] += a[i] * bb[j];
        }
        __syncthreads();
    }

    float4 bias = *reinterpret_cast<const float4*>(&bo[n0 + tx * 4]);
#pragma unroll
    for (int i = 0; i < 8; i++) {
        int bsrow = row0 + ty * 8 + i;
        float4 v4 = make_float4(acc[i][0] + bias.x, acc[i][1] + bias.y,
                                acc[i][2] + bias.z, acc[i][3] + bias.w);
        *reinterpret_cast<float4*>(&out[(size_t)bsrow * DD + n0 + tx * 4]) = v4;
    }
}

// =====================================================================
extern "C" void kernel_launch(void* const* d_in, const int* in_sizes, int n_in,
                              void* d_out, int out_size)
{
    const float* x  = (const float*)d_in[0];
    const float* wq = (const float*)d_in[1];
    const float* wk = (const float*)d_in[2];
    const float* wv = (const float*)d_in[3];
    const float* wo = (const float*)d_in[4];
    const float* bo = (const float*)d_in[5];
    float* out = (float*)d_out;

    cudaFuncSetAttribute(attn_tf32_kernel,
                         cudaFuncAttributeMaxDynamicSharedMemorySize, ATTN_SMEM_BYTES);

    qkv_kernel<<<dim3(DD / 64, BSR / 128, 3), 256>>>(x, wq, wk, wv);
    attn_tf32_kernel<<<dim3(SS / 128, BB * HH), 256, ATTN_SMEM_BYTES>>>();
    out_proj_kernel<<<dim3(DD / 64, BSR / 128), 256>>>(wo, bo, out);
}

// round 3
// speedup vs baseline: 3.8442x; 1.5476x over previous
#include <cuda_runtime.h>
#include <math.h>

#define BB 8
#define SS 2048
#define DD 256
#define HH 4
#define DHH 64
#define BSR (BB*SS)   // 16384 rows

// ---------------- scratch (no allocations allowed) ----------------
__device__ float g_q[BB*HH*SS*DHH];
__device__ float g_k[BB*HH*SS*DHH];
__device__ float g_v[BB*HH*SS*DHH];
__device__ float g_ctx[BSR*DD];

// round-to-nearest tf32 (keeps bits in a float register)
__device__ __forceinline__ float t32(float x) {
    unsigned u;
    asm("cvt.rna.tf32.f32 %0, %1;" : "=r"(u) : "f"(x));
    return __uint_as_float(u);
}

__device__ __forceinline__ void mma_tf32(float* c, const unsigned* a, const unsigned* b) {
    asm volatile(
        "mma.sync.aligned.m16n8k8.row.col.f32.tf32.tf32.f32 "
        "{%0,%1,%2,%3}, {%4,%5,%6,%7}, {%8,%9}, {%0,%1,%2,%3};"
        : "+f"(c[0]), "+f"(c[1]), "+f"(c[2]), "+f"(c[3])
        : "r"(a[0]), "r"(a[1]), "r"(a[2]), "r"(a[3]), "r"(b[0]), "r"(b[1]));
}

// =====================================================================
// QKV projection (fp32 SIMT): out_z[b,h,s,dh] = sum_k x[bs,k] * w_z[k, h*64+dh]
// grid: (DD/64, BSR/128, 3), 256 threads.
// =====================================================================
__global__ __launch_bounds__(256) void qkv_kernel(
    const float* __restrict__ x,
    const float* __restrict__ wq,
    const float* __restrict__ wk,
    const float* __restrict__ wv)
{
    __shared__ float Xt[16][129];
    __shared__ float Ws[16][64];

    const int tid = threadIdx.x;
    const int ty = tid >> 4;
    const int tx = tid & 15;
    const int n0 = blockIdx.x * 64;
    const int row0 = blockIdx.y * 128;
    const int z = blockIdx.z;

    const float* w = (z == 0) ? wq : (z == 1) ? wk : wv;
    float* outp = (z == 0) ? g_q : (z == 1) ? g_k : g_v;

    float acc[8][4];
#pragma unroll
    for (int i = 0; i < 8; i++)
#pragma unroll
        for (int j = 0; j < 4; j++) acc[i][j] = 0.f;

    for (int k0 = 0; k0 < DD; k0 += 16) {
#pragma unroll
        for (int r = 0; r < 2; r++) {
            int f = tid + 256 * r;
            int row = f >> 2;
            int kg = f & 3;
            float4 v4 = *reinterpret_cast<const float4*>(&x[(row0 + row) * DD + k0 + kg * 4]);
            Xt[kg * 4 + 0][row] = v4.x;
            Xt[kg * 4 + 1][row] = v4.y;
            Xt[kg * 4 + 2][row] = v4.z;
            Xt[kg * 4 + 3][row] = v4.w;
        }
        {
            int rowk = tid >> 4;
            int c4 = tid & 15;
            *reinterpret_cast<float4*>(&Ws[rowk][c4 * 4]) =
                *reinterpret_cast<const float4*>(&w[(k0 + rowk) * DD + n0 + c4 * 4]);
        }
        __syncthreads();
#pragma unroll
        for (int kk = 0; kk < 16; kk++) {
            float a[8];
#pragma unroll
            for (int i = 0; i < 8; i++) a[i] = Xt[kk][ty * 8 + i];
            float4 b4 = *reinterpret_cast<const float4*>(&Ws[kk][tx * 4]);
            float bb[4] = {b4.x, b4.y, b4.z, b4.w};
#pragma unroll
            for (int i = 0; i < 8; i++)
#pragma unroll
                for (int j = 0; j < 4; j++) acc[i][j] += a[i] * bb[j];
        }
        __syncthreads();
    }

    const int h = n0 / DHH;
#pragma unroll
    for (int i = 0; i < 8; i++) {
        int bsrow = row0 + ty * 8 + i;
        int b_ = bsrow >> 11;
        int s_ = bsrow & (SS - 1);
        float4 v4 = make_float4(acc[i][0], acc[i][1], acc[i][2], acc[i][3]);
        *reinterpret_cast<float4*>(&outp[(((b_ * HH + h) * SS) + s_) * DHH + tx * 4]) = v4;
    }
}

// =====================================================================
// Flash attention with tf32 tensor-core MMA.
// grid: (S/128, B*H), 256 threads (8 warps, each owns 16 q-rows).
// Q-tile 128, K-tile 64. Dynamic smem:
//   QP (Q then P) : 128 x stride68  = 8704 floats
//   Ks            :  64 x stride68  = 4352 floats
//   Vs            :  64 x stride72  = 4608 floats
// total 17664 floats = 70656 B
// =====================================================================
#define ATTN_SMEM_BYTES 70656

__global__ __launch_bounds__(256) void attn_tf32_kernel()
{
    extern __shared__ float sm[];
    float* QP = sm;                 // stride 68
    float* Ks = sm + 8704;          // stride 68
    float* Vs = sm + 13056;         // stride 72

    const int tid = threadIdx.x;
    const int lane = tid & 31;
    const int warp = tid >> 5;
    const int gr = lane >> 2;       // 0..7
    const int gc = lane & 3;        // 0..3
    const int wq = warp * 16;

    const int q0 = blockIdx.x * 128;
    const int bh = blockIdx.y;

    const float* qptr = g_q + (size_t)bh * SS * DHH;
    const float* kptr = g_k + (size_t)bh * SS * DHH;
    const float* vptr = g_v + (size_t)bh * SS * DHH;

    // ---- load Q tile (scaled by 1/sqrt(dh), tf32-rounded) ----
#pragma unroll
    for (int r = 0; r < 8; r++) {
        int f = tid + 256 * r;
        int row = f >> 4;
        int c4 = f & 15;
        float4 v4 = *reinterpret_cast<const float4*>(&qptr[(q0 + row) * DHH + c4 * 4]);
        float4 w4 = make_float4(t32(v4.x * 0.125f), t32(v4.y * 0.125f),
                                t32(v4.z * 0.125f), t32(v4.w * 0.125f));
        *reinterpret_cast<float4*>(&QP[row * 68 + c4 * 4]) = w4;
    }
    __syncthreads();

    // ---- extract Q fragments (register-resident for whole K loop) ----
    unsigned qa[8][4];
#pragma unroll
    for (int ks = 0; ks < 8; ks++) {
        int col = ks * 8 + gc;
        qa[ks][0] = __float_as_uint(QP[(wq + gr) * 68 + col]);
        qa[ks][1] = __float_as_uint(QP[(wq + 8 + gr) * 68 + col]);
        qa[ks][2] = __float_as_uint(QP[(wq + gr) * 68 + col + 4]);
        qa[ks][3] = __float_as_uint(QP[(wq + 8 + gr) * 68 + col + 4]);
    }

    float o[8][4];
#pragma unroll
    for (int nt = 0; nt < 8; nt++)
#pragma unroll
        for (int j = 0; j < 4; j++) o[nt][j] = 0.f;
    float m0 = -INFINITY, m1 = -INFINITY, l0 = 0.f, l1 = 0.f;

    for (int kt = 0; kt < SS / 64; kt++) {
        const int k0 = kt * 64;
        __syncthreads();   // Q-frag extraction (iter 0) / prior-iter Ks,Vs reads done

        // ---- load K, V tiles (tf32-rounded) ----
#pragma unroll
        for (int r = 0; r < 4; r++) {
            int f = tid + 256 * r;
            int row = f >> 4;
            int c4 = f & 15;
            float4 kv = *reinterpret_cast<const float4*>(&kptr[(k0 + row) * DHH + c4 * 4]);
            float4 kw = make_float4(t32(kv.x), t32(kv.y), t32(kv.z), t32(kv.w));
            *reinterpret_cast<float4*>(&Ks[row * 68 + c4 * 4]) = kw;
            float4 vv = *reinterpret_cast<const float4*>(&vptr[(k0 + row) * DHH + c4 * 4]);
            float4 vw = make_float4(t32(vv.x), t32(vv.y), t32(vv.z), t32(vv.w));
            *reinterpret_cast<float4*>(&Vs[row * 72 + c4 * 4]) = vw;
        }
        __syncthreads();

        // ---- S = Q @ K^T  (m16 x n64 x k64 per warp) ----
        float s[8][4];
#pragma unroll
        for (int nt = 0; nt < 8; nt++) {
            s[nt][0] = 0.f; s[nt][1] = 0.f; s[nt][2] = 0.f; s[nt][3] = 0.f;
#pragma unroll
            for (int ks = 0; ks < 8; ks++) {
                unsigned b[2];
                b[0] = __float_as_uint(Ks[(nt * 8 + gr) * 68 + ks * 8 + gc]);
                b[1] = __float_as_uint(Ks[(nt * 8 + gr) * 68 + ks * 8 + gc + 4]);
                mma_tf32(s[nt], qa[ks], b);
            }
        }

        // ---- online softmax (rows r0 = wq+gr, r1 = wq+8+gr) ----
        float mx0 = -INFINITY, mx1 = -INFINITY;
#pragma unroll
        for (int nt = 0; nt < 8; nt++) {
            mx0 = fmaxf(mx0, fmaxf(s[nt][0], s[nt][1]));
            mx1 = fmaxf(mx1, fmaxf(s[nt][2], s[nt][3]));
        }
        mx0 = fmaxf(mx0, __shfl_xor_sync(0xffffffffu, mx0, 1));
        mx0 = fmaxf(mx0, __shfl_xor_sync(0xffffffffu, mx0, 2));
        mx1 = fmaxf(mx1, __shfl_xor_sync(0xffffffffu, mx1, 1));
        mx1 = fmaxf(mx1, __shfl_xor_sync(0xffffffffu, mx1, 2));

        float m0n = fmaxf(m0, mx0);
        float m1n = fmaxf(m1, mx1);
        float a0 = __expf(m0 - m0n);
        float a1 = __expf(m1 - m1n);

        float rs0 = 0.f, rs1 = 0.f;
#pragma unroll
        for (int nt = 0; nt < 8; nt++) {
            float p0 = __expf(s[nt][0] - m0n);
            float p1 = __expf(s[nt][1] - m0n);
            float p2 = __expf(s[nt][2] - m1n);
            float p3 = __expf(s[nt][3] - m1n);
            rs0 += p0 + p1;
            rs1 += p2 + p3;
            float2 lo = make_float2(t32(p0), t32(p1));
            float2 hi = make_float2(t32(p2), t32(p3));
            *reinterpret_cast<float2*>(&QP[(wq + gr) * 68 + nt * 8 + gc * 2]) = lo;
            *reinterpret_cast<float2*>(&QP[(wq + 8 + gr) * 68 + nt * 8 + gc * 2]) = hi;
        }
        rs0 += __shfl_xor_sync(0xffffffffu, rs0, 1);
        rs0 += __shfl_xor_sync(0xffffffffu, rs0, 2);
        rs1 += __shfl_xor_sync(0xffffffffu, rs1, 1);
        rs1 += __shfl_xor_sync(0xffffffffu, rs1, 2);

        m0 = m0n; m1 = m1n;
        l0 = l0 * a0 + rs0;
        l1 = l1 * a1 + rs1;
#pragma unroll
        for (int nt = 0; nt < 8; nt++) {
            o[nt][0] *= a0; o[nt][1] *= a0;
            o[nt][2] *= a1; o[nt][3] *= a1;
        }
        __syncwarp();   // P rows of this warp written by this warp only

        // ---- O += P @ V  (m16 x n64 x k64 per warp) ----
#pragma unroll
        for (int ks = 0; ks < 8; ks++) {
            unsigned pa[4];
            int col = ks * 8 + gc;
            pa[0] = __float_as_uint(QP[(wq + gr) * 68 + col]);
            pa[1] = __float_as_uint(QP[(wq + 8 + gr) * 68 + col]);
            pa[2] = __float_as_uint(QP[(wq + gr) * 68 + col + 4]);
            pa[3] = __float_as_uint(QP[(wq + 8 + gr) * 68 + col + 4]);
#pragma unroll
            for (int nt = 0; nt < 8; nt++) {
                unsigned b[2];
                b[0] = __float_as_uint(Vs[(ks * 8 + gc) * 72 + nt * 8 + gr]);
                b[1] = __float_as_uint(Vs[(ks * 8 + gc + 4) * 72 + nt * 8 + gr]);
                mma_tf32(o[nt], pa, b);
            }
        }
    }

    // ---- epilogue: normalize, write ctx[bs, h*64 + dh] ----
    const float inv0 = 1.0f / l0;
    const float inv1 = 1.0f / l1;
    const int b_ = bh >> 2;
    const int h_ = bh & 3;
    const int row0 = q0 + wq + gr;
    const int row1 = row0 + 8;
#pragma unroll
    for (int nt = 0; nt < 8; nt++) {
        int col = h_ * DHH + nt * 8 + gc * 2;
        float2 lo = make_float2(o[nt][0] * inv0, o[nt][1] * inv0);
        float2 hi = make_float2(o[nt][2] * inv1, o[nt][3] * inv1);
        *reinterpret_cast<float2*>(&g_ctx[(size_t)(b_ * SS + row0) * DD + col]) = lo;
        *reinterpret_cast<float2*>(&g_ctx[(size_t)(b_ * SS + row1) * DD + col]) = hi;
    }
}

// =====================================================================
// Output projection: out = ctx @ w_o + b_o (fp32 SIMT)
// =====================================================================
__global__ __launch_bounds__(256) void out_proj_kernel(
    const float* __restrict__ wo,
    const float* __restrict__ bo,
    float* __restrict__ out)
{
    __shared__ float Xt[16][129];
    __shared__ float Ws[16][64];

    const int tid = threadIdx.x;
    const int ty = tid >> 4;
    const int tx = tid & 15;
    const int n0 = blockIdx.x * 64;
    const int row0 = blockIdx.y * 128;

    float acc[8][4];
#pragma unroll
    for (int i = 0; i < 8; i++)
#pragma unroll
        for (int j = 0; j < 4; j++) acc[i][j] = 0.f;

    for (int k0 = 0; k0 < DD; k0 += 16) {
#pragma unroll
        for (int r = 0; r < 2; r++) {
            int f = tid + 256 * r;
            int row = f >> 2;
            int kg = f & 3;
            float4 v4 = *reinterpret_cast<const float4*>(&g_ctx[(size_t)(row0 + row) * DD + k0 + kg * 4]);
            Xt[kg * 4 + 0][row] = v4.x;
            Xt[kg * 4 + 1][row] = v4.y;
            Xt[kg * 4 + 2][row] = v4.z;
            Xt[kg * 4 + 3][row] = v4.w;
        }
        {
            int rowk = tid >> 4;
            int c4 = tid & 15;
            *reinterpret_cast<float4*>(&Ws[rowk][c4 * 4]) =
                *reinterpret_cast<const float4*>(&wo[(k0 + rowk) * DD + n0 + c4 * 4]);
        }
        __syncthreads();
#pragma unroll
        for (int kk = 0; kk < 16; kk++) {
            float a[8];
#pragma unroll
            for (int i = 0; i < 8; i++) a[i] = Xt[kk][ty * 8 + i];
            float4 b4 = *reinterpret_cast<const float4*>(&Ws[kk][tx * 4]);
            float bb[4] = {b4.x, b4.y, b4.z, b4.w};
#pragma unroll
            for (int i = 0; i < 8; i++)
#pragma unroll
                for (int j = 0; j < 4; j++) acc[i][j] += a[i] * bb[j];
        }
        __syncthreads();
    }

    float4 bias = *reinterpret_cast<const float4*>(&bo[n0 + tx * 4]);
#pragma unroll
    for (int i = 0; i < 8; i++) {
        int bsrow = row0 + ty * 8 + i;
        float4 v4 = make_float4(acc[i][0] + bias.x, acc[i][1] + bias.y,
                                acc[i][2] + bias.z, acc[i][3] + bias.w);
        *reinterpret_cast<float4*>(&out[(size_t)bsrow * DD + n0 + tx * 4]) = v4;
    }
}

// =====================================================================
extern "C" void kernel_launch(void* const* d_in, const int* in_sizes, int n_in,
                              void* d_out, int out_size)
{
    const float* x  = (const float*)d_in[0];
    const float* wq = (const float*)d_in[1];
    const float* wk = (const float*)d_in[2];
    const float* wv = (const float*)d_in[3];
    const float* wo = (const float*)d_in[4];
    const float* bo = (const float*)d_in[5];
    float* out = (float*)d_out;

    cudaFuncSetAttribute(attn_tf32_kernel,
                         cudaFuncAttributeMaxDynamicSharedMemorySize, ATTN_SMEM_BYTES);

    qkv_kernel<<<dim3(DD / 64, BSR / 128, 3), 256>>>(x, wq, wk, wv);
    attn_tf32_kernel<<<dim3(SS / 128, BB * HH), 256, ATTN_SMEM_BYTES>>>();
    out_proj_kernel<<<dim3(DD / 64, BSR / 128), 256>>>(wo, bo, out);
}